// round 1
// baseline (speedup 1.0000x reference)
#include <cuda_runtime.h>
#include <cuda_bf16.h>

// Problem constants (fixed by setup_inputs): B=2, N=1024, D_IN=D_OUT=8, C=32
#define TA 16          // a-tile per block
#define TB 128         // b-tile per smem stage
#define NC 32          // number of radial basis centers
#define NTHREADS 512   // TA warps * 32 lanes(c)

__global__ __launch_bounds__(NTHREADS, 1)
void conv_cc_kernel(const float* __restrict__ features,   // [B,N,8]
                    const float* __restrict__ geometry,   // [B,N,3]
                    const float* __restrict__ Wm,         // [C,8,8]
                    const int*   __restrict__ n_norm_p,   // scalar
                    float* __restrict__ out,              // [B,N,8]
                    int N)
{
    __shared__ float  s_ga[TA * 3];        // geometry of this block's a-points
    __shared__ float  s_gb[TB * 3];        // geometry of current b-tile
    __shared__ float  s_t [TA * TB];       // t = d(a,b) / width
    __shared__ float4 s_feat[TB * 2];      // features of current b-tile, [b][2xfloat4]
    __shared__ float  s_Wt[64 * NC];       // W transposed: [i*8+j][c]  (conflict-free per-lane reads)

    const int tid  = threadIdx.x;
    const int w    = tid >> 5;     // warp id = a_local in [0,TA)
    const int lane = tid & 31;     // lane   = c in [0,32)
    const int z    = blockIdx.y;
    const int a0   = blockIdx.x * TA;

    const float inv_width = 31.0f / 3.5f;  // centers[k] = k * (3.5/31)
    const float fc = (float)lane;

    // Stage W transposed into smem: global [c][ij] -> smem [ij][c]
    for (int idx = tid; idx < 64 * NC; idx += NTHREADS) {
        int c  = idx >> 6;
        int ij = idx & 63;
        s_Wt[ij * NC + c] = Wm[idx];
    }
    // Stage this block's a-geometry
    if (tid < TA * 3)
        s_ga[tid] = geometry[(size_t)(z * N + a0) * 3 + tid];

    float G[8];
    #pragma unroll
    for (int j = 0; j < 8; j++) G[j] = 0.0f;

    const float* featz = features + (size_t)z * N * 8;
    const float* geomz = geometry + (size_t)z * N * 3;

    for (int b0 = 0; b0 < N; b0 += TB) {
        __syncthreads();   // protects s_feat/s_gb/s_t reuse + first-iter staging

        // Stage feature tile (1024 floats) and b-geometry tile (384 floats)
        {
            float* s_feat_f = (float*)s_feat;
            for (int idx = tid; idx < TB * 8; idx += NTHREADS)
                s_feat_f[idx] = featz[b0 * 8 + idx];
            for (int idx = tid; idx < TB * 3; idx += NTHREADS)
                s_gb[idx] = geomz[b0 * 3 + idx];
        }
        __syncthreads();

        // Precompute t = d/width for the TA x TB pair tile (shared across 32 c-lanes)
        for (int idx = tid; idx < TA * TB; idx += NTHREADS) {
            int a  = idx >> 7;          // idx / TB  (TB = 128)
            int bb = idx & (TB - 1);
            float dx = s_ga[a * 3 + 0] - s_gb[bb * 3 + 0];
            float dy = s_ga[a * 3 + 1] - s_gb[bb * 3 + 1];
            float dz = s_ga[a * 3 + 2] - s_gb[bb * 3 + 2];
            float d  = sqrtf(dx * dx + dy * dy + dz * dz + 1e-12f);
            s_t[idx] = d * inv_width;
        }
        __syncthreads();

        // Hot loop: per (a=w, c=lane), accumulate G[j] += basis * feat[b][j]
        const float* tw = &s_t[w * TB];
        #pragma unroll 4
        for (int b = 0; b < TB; b++) {
            float arg = tw[b] - fc;               // uniform LDS (broadcast)
            float e   = __expf(-arg * arg);       // 2 FMUL + MUFU.EX2
            float4 f0 = s_feat[b * 2 + 0];        // broadcast LDS.128
            float4 f1 = s_feat[b * 2 + 1];
            G[0] += e * f0.x;  G[1] += e * f0.y;  G[2] += e * f0.z;  G[3] += e * f0.w;
            G[4] += e * f1.x;  G[5] += e * f1.y;  G[6] += e * f1.z;  G[7] += e * f1.w;
        }
    }

    // n_norm: robust to int32/int64/float32 encoding of the scalar 1024
    int nv = *n_norm_p;
    float nf = (nv > 0 && nv < (1 << 26)) ? (float)nv : __int_as_float(nv);
    const float scale = rsqrtf(nf);

    // Epilogue: out[z, a0+w, i] = scale * sum_{c,j} W[c,i,j] * G[c-lane][j]
    #pragma unroll
    for (int i = 0; i < 8; i++) {
        float p = 0.0f;
        #pragma unroll
        for (int j = 0; j < 8; j++)
            p += s_Wt[(i * 8 + j) * NC + lane] * G[j];   // lanes -> consecutive banks
        #pragma unroll
        for (int off = 16; off; off >>= 1)
            p += __shfl_xor_sync(0xffffffffu, p, off);   // reduce over c
        if (lane == i)
            out[(size_t)(z * N + a0 + w) * 8 + i] = p * scale;
    }
}

extern "C" void kernel_launch(void* const* d_in, const int* in_sizes, int n_in,
                              void* d_out, int out_size)
{
    const float* features = (const float*)d_in[0];   // [B,N,8]
    const float* geometry = (const float*)d_in[1];   // [B,N,3]
    const float* Wm       = (const float*)d_in[2];   // [32,8,8]
    const int*   n_norm   = (const int*)d_in[3];     // scalar

    const int N = 1024;
    const int B = in_sizes[1] / (3 * N);             // geometry elems = B*N*3

    dim3 grid(N / TA, B);
    conv_cc_kernel<<<grid, NTHREADS>>>(features, geometry, Wm, n_norm,
                                       (float*)d_out, N);
}

// round 2
// speedup vs baseline: 1.1265x; 1.1265x over previous
#include <cuda_runtime.h>
#include <cuda_bf16.h>

// Problem constants (fixed by setup_inputs): B=2, N=1024, D_IN=D_OUT=8, C=32
#define NPT   1024
#define NC    32
#define TA    16        // a's per block (one warp per a)
#define TB    32        // b-tile per smem stage
#define NTHREADS 512    // TA * 32
#define CW    8         // c-window width (centers kept per pair)

// Scratch for the pre-contracted operand P[z][b][c][i] (i fastest).
// Sized for up to 4 batches of N=1024.
__device__ float g_P[4 * NPT * NC * 8];

// ---------------------------------------------------------------------------
// Kernel 1: P[z,b,c,i] = sum_j W[c,i,j] * feat[z,b,j]
// One block per (z,b); 256 threads = 32 c x 8 i.
// ---------------------------------------------------------------------------
__global__ __launch_bounds__(256, 4)
void compute_P_kernel(const float* __restrict__ features,  // [B,N,8]
                      const float* __restrict__ Wm,        // [32,8,8]
                      float* __restrict__ P)
{
    __shared__ float sW[NC * 64];
    __shared__ float sf[8];
    const int zb  = blockIdx.x;
    const int tid = threadIdx.x;

    for (int i = tid; i < NC * 64; i += 256) sW[i] = Wm[i];
    if (tid < 8) sf[tid] = features[zb * 8 + tid];
    __syncthreads();

    const int c = tid >> 3, i = tid & 7;
    const float* wr = &sW[c * 64 + i * 8];
    float p = 0.0f;
    #pragma unroll
    for (int j = 0; j < 8; j++) p += wr[j] * sf[j];
    P[(size_t)zb * 256 + tid] = p;
}

// ---------------------------------------------------------------------------
// Kernel 2: fused windowed radial conv.
//   out[z,a,i] = (1/sqrt(N)) * sum_b sum_{c in window(t_ab)} e(t_ab,c) * P[z,b,c,i]
// Block = (z, 16 a's). Warp = one a. Lane = c_off*4 + ipair.
// ---------------------------------------------------------------------------
__global__ __launch_bounds__(NTHREADS, 1)
void conv_window_kernel(const float* __restrict__ geometry,  // [B,N,3]
                        const float* __restrict__ P,         // [B,N,32,8]
                        const int*   __restrict__ n_norm_p,
                        float* __restrict__ out,             // [B,N,8]
                        int N)
{
    __shared__ float  s_P[TB * 256];        // 32 KB: P tile [b][c][i]
    __shared__ float2 s_meta[TA * TB];      // {arg0 = t - c0f, int_as_float(c0*32 bytes)}

    const int tid   = threadIdx.x;
    const int w     = tid >> 5;              // warp = a_local
    const int lane  = tid & 31;
    const int z     = blockIdx.y;
    const int a0    = blockIdx.x * TA;

    const float inv_width = (float)(NC - 1) / 3.5f;   // centers[k] = k * width
    const float coff_f    = (float)(lane >> 2);       // this lane's c offset in window
    const int   lane_po   = (lane >> 2) * 32 + (lane & 3) * 8;  // byte offset: c_off*32B + ipair*8B

    const float* geomz = geometry + (size_t)z * N * 3;
    const float* Pz    = P + (size_t)z * N * 256;

    // per-thread fixed a-geometry (for the meta pass: this thread's a = its warp)
    const int am = tid >> 5;                 // == w
    const float ax = geomz[(a0 + am) * 3 + 0];
    const float ay = geomz[(a0 + am) * 3 + 1];
    const float az = geomz[(a0 + am) * 3 + 2];
    const int bb = tid & (TB - 1);           // this thread's b slot in the meta pass

    unsigned long long acc = 0ull;           // packed f32x2 accumulator (one i-pair)

    for (int b0 = 0; b0 < N; b0 += TB) {
        __syncthreads();   // previous tile's s_P / s_meta fully consumed

        // Stage P tile: TB*256 floats = 2048 float4, 4 per thread
        {
            const float4* src = (const float4*)(Pz + (size_t)b0 * 256);
            float4* dst = (float4*)s_P;
            #pragma unroll
            for (int k = 0; k < 4; k++)
                dst[tid + k * NTHREADS] = src[tid + k * NTHREADS];
        }
        // Meta: one (a,b) pair per thread
        {
            const int bg = b0 + bb;
            float dx = ax - geomz[bg * 3 + 0];
            float dy = ay - geomz[bg * 3 + 1];
            float dz = az - geomz[bg * 3 + 2];
            float d  = sqrtf(dx * dx + dy * dy + dz * dz + 1e-12f);
            float t  = d * inv_width;
            float c0f = fmaxf(fminf(floorf(t) - 3.0f, (float)(NC - CW)), 0.0f);
            int   c0  = (int)c0f;
            s_meta[am * TB + bb] = make_float2(t - c0f, __int_as_float(c0 * 32));
        }
        __syncthreads();

        // Hot loop: this warp's a, all TB b's
        const float4* m4 = (const float4*)(s_meta + w * TB);   // 2 b's per float4
        const char* sPb = (const char*)s_P;
        #pragma unroll 8
        for (int b2 = 0; b2 < TB / 2; b2++) {
            float4 mm = m4[b2];
            #pragma unroll
            for (int h = 0; h < 2; h++) {
                float arg0 = h ? mm.z : mm.x;
                int   offb = __float_as_int(h ? mm.w : mm.y);
                float arg  = arg0 - coff_f;
                float e    = __expf(-arg * arg);
                unsigned int eu = __float_as_uint(e);
                unsigned long long e2;
                asm("mov.b64 %0, {%1, %1};" : "=l"(e2) : "r"(eu));
                unsigned long long p2 =
                    *(const unsigned long long*)(sPb + (b2 * 2 + h) * 1024 + offb + lane_po);
                asm("fma.rn.f32x2 %0, %1, %2, %0;" : "+l"(acc) : "l"(e2), "l"(p2));
            }
        }
    }

    // n_norm: robust to int32 or float32 encoding of the scalar
    int nv = *n_norm_p;
    float nf = (nv > 0 && nv < (1 << 26)) ? (float)nv : __int_as_float(nv);
    const float scale = rsqrtf(nf);

    // Reduce over the 8 c_off lanes sharing each i-pair (same lane&3 class)
    unsigned int lou, hiu;
    asm("mov.b64 {%0, %1}, %2;" : "=r"(lou), "=r"(hiu) : "l"(acc));
    float lo = __uint_as_float(lou), hi = __uint_as_float(hiu);
    #pragma unroll
    for (int off = 4; off < 32; off <<= 1) {
        lo += __shfl_xor_sync(0xffffffffu, lo, off);
        hi += __shfl_xor_sync(0xffffffffu, hi, off);
    }
    if (lane < 4) {
        float2* orow = (float2*)(out + (size_t)(z * N + a0 + w) * 8);
        orow[lane] = make_float2(lo * scale, hi * scale);
    }
}

extern "C" void kernel_launch(void* const* d_in, const int* in_sizes, int n_in,
                              void* d_out, int out_size)
{
    const float* features = (const float*)d_in[0];   // [B,N,8]
    const float* geometry = (const float*)d_in[1];   // [B,N,3]
    const float* Wm       = (const float*)d_in[2];   // [32,8,8]
    const int*   n_norm   = (const int*)d_in[3];     // scalar

    const int N = NPT;
    const int B = in_sizes[1] / (3 * N);

    float* P;
    cudaGetSymbolAddress((void**)&P, g_P);

    compute_P_kernel<<<B * N, 256>>>(features, Wm, P);

    dim3 grid(N / TA, B);
    conv_window_kernel<<<grid, NTHREADS>>>(geometry, P, n_norm, (float*)d_out, N);
}